// round 16
// baseline (speedup 1.0000x reference)
#include <cuda_runtime.h>
#include <cuda_bf16.h>
#include <cstdint>

#define N_NODES 50000
#define E_EDGES 800000
#define DIM     128
#define G_GRAPHS 128
#define C_CLASSES 10
#define TILE_M  128
#define SMP2    136                     // padded bf16 row stride (272 B)
#define TILE_ELEMS (TILE_M * SMP2)      // 17408 bf16
#define TILE_BYTES (TILE_ELEMS * 2)     // 34816 B

// ---------------------------------------------------------------------------
// Device scratch (no allocation allowed)
// ---------------------------------------------------------------------------
__device__ float g_relA[N_NODES * DIM];
__device__ float g_relB[N_NODES * DIM];
__device__ float g_rtA [N_NODES * DIM];
__device__ float g_rtB [N_NODES * DIM];
__device__ float g_pool[G_GRAPHS * DIM];
__device__ float g_cnt [G_GRAPHS];
// CSR scratch
__device__ int g_deg   [N_NODES];
__device__ int g_rowptr[N_NODES + 1];
__device__ int g_cursor[N_NODES];
__device__ int g_csrc  [E_EDGES];
// Pre-converted W images, padded rows (SMP2), order per layer:
// [2*layer][0]=rel hi, [2*layer][1]=rel lo, [2*layer+1][0]=root hi, [1]=root lo
__device__ __nv_bfloat16 g_wimg[8][2][TILE_ELEMS];

// ---------------------------------------------------------------------------
// helpers
// ---------------------------------------------------------------------------
__device__ __forceinline__ uint32_t smem_u32(const void* p) {
    uint32_t a;
    asm("{ .reg .u64 t; cvta.to.shared.u64 t, %1; cvt.u32.u64 %0, t; }"
        : "=r"(a) : "l"(p));
    return a;
}

// split fp32 pair -> bf16 hi pair + bf16 lo pair (packed: first arg in low half)
__device__ __forceinline__ void split2(float a, float b, uint32_t& hi, uint32_t& lo) {
    asm("cvt.rn.bf16x2.f32 %0, %1, %2;" : "=r"(hi) : "f"(b), "f"(a));
    float ra = a - __uint_as_float(hi << 16);
    float rb = b - __uint_as_float(hi & 0xffff0000u);
    asm("cvt.rn.bf16x2.f32 %0, %1, %2;" : "=r"(lo) : "f"(rb), "f"(ra));
}

__device__ __forceinline__ void ldsm_x4(uint32_t& a0, uint32_t& a1,
                                        uint32_t& a2, uint32_t& a3, uint32_t addr) {
    asm volatile("ldmatrix.sync.aligned.m8n8.x4.shared.b16 {%0,%1,%2,%3}, [%4];"
                 : "=r"(a0), "=r"(a1), "=r"(a2), "=r"(a3) : "r"(addr));
}
__device__ __forceinline__ void mma_bf16(float* c, uint32_t a0, uint32_t a1,
                                         uint32_t a2, uint32_t a3,
                                         uint32_t b0, uint32_t b1) {
    asm volatile("mma.sync.aligned.m16n8k16.row.col.f32.bf16.bf16.f32 "
                 "{%0,%1,%2,%3}, {%4,%5,%6,%7}, {%8,%9}, {%0,%1,%2,%3};"
                 : "+f"(c[0]), "+f"(c[1]), "+f"(c[2]), "+f"(c[3])
                 : "r"(a0), "r"(a1), "r"(a2), "r"(a3), "r"(b0), "r"(b1));
}

// ---------------------------------------------------------------------------
// W pre-convert: 8 blocks, one per (layer, mat). fp32 -> bf16 hi/lo, padded rows.
// ---------------------------------------------------------------------------
struct WPtrs { const float* p[8]; };

__global__ __launch_bounds__(256)
void w_convert_kernel(WPtrs wp)
{
    int b = blockIdx.x;
    const float* src = wp.p[b];
    __nv_bfloat16* hi_img = &g_wimg[b][0][0];
    __nv_bfloat16* lo_img = &g_wimg[b][1][0];
    int tid = threadIdx.x;
    #pragma unroll
    for (int it = 0; it < 16; it++) {
        int id = tid + it * 256;        // 0..4095 quads
        int r = id >> 5;
        int c = (id & 31) * 4;
        float4 v = *(const float4*)(src + r * DIM + c);
        uint32_t h0, l0, h1, l1;
        split2(v.x, v.y, h0, l0);
        split2(v.z, v.w, h1, l1);
        *(uint2*)(hi_img + r * SMP2 + c) = make_uint2(h0, h1);
        *(uint2*)(lo_img + r * SMP2 + c) = make_uint2(l0, l1);
    }
}

// ---------------------------------------------------------------------------
// Fused layer kernel: one block per 128-row slab.
//   A[r,:] = (layer==0) ? x[r,:]
//          : relu(rt_prev[r,:] + sum_{s in in(r)} rel_prev[s,:])   <- gather fused
//   rel_out[r,o] = A[r,:] . Wrel[o,:]
//   rt_out [r,o] = A[r,:] . Wroot[o,:] + bias[o]
// A staged PER WARP (each warp's mma uses only its own 16 rows), so gather
// overlaps with other warps' HMMA. Split-bf16, 3 terms (fp32 accum).
// smem tiles (padded SMP2): [0]=Ahi [1]=Alo [2]=Wrel_hi [3]=Wrel_lo
// [4]=Wroot_hi [5]=Wroot_lo.
// ---------------------------------------------------------------------------
__global__ __launch_bounds__(256, 1)
void gemm_fused_kernel(const float* __restrict__ x,
                       const float* __restrict__ rel_prev,
                       const float* __restrict__ rt_prev,
                       const float* __restrict__ bias,
                       float* __restrict__ rel_out,
                       float* __restrict__ rt_out,
                       int layer)
{
    extern __shared__ __align__(16) char sm[];
    __nv_bfloat16* tiles = (__nv_bfloat16*)sm;
    const uint32_t smb = smem_u32(sm);
    const int tid  = threadIdx.x;
    const int wid  = tid >> 5;
    const int lane = tid & 31;
    const int m0   = blockIdx.x * TILE_M;

    // --- copy 4 W tiles (contiguous in g_wimg), block-wide, then ONE sync ---
    {
        const uint4* src = (const uint4*)&g_wimg[2 * layer][0][0];
        uint4* dst = (uint4*)(tiles + 2 * TILE_ELEMS);
        #pragma unroll
        for (int it = 0; it < 34; it++)
            dst[tid + it * 256] = src[tid + it * 256];   // 8704 uint4 total
    }
    __syncthreads();

    // --- per-warp A stage: gather + relu + split for this warp's 16 rows ---
    {
        __nv_bfloat16* ahi = tiles;
        __nv_bfloat16* alo = tiles + TILE_ELEMS;
        #pragma unroll 1
        for (int i = 0; i < 16; i++) {
            int r  = wid * 16 + i;
            int gr = m0 + r;
            float4 v = make_float4(0.f, 0.f, 0.f, 0.f);
            if (gr < N_NODES) {
                if (layer == 0) {
                    v = ((const float4*)x)[gr * 32 + lane];
                } else {
                    v = ((const float4*)rt_prev)[gr * 32 + lane];
                    int beg = g_rowptr[gr];
                    int end = g_rowptr[gr + 1];
                    int j = beg;
                    for (; j + 4 <= end; j += 4) {
                        int s0 = g_csrc[j + 0], s1 = g_csrc[j + 1];
                        int s2 = g_csrc[j + 2], s3 = g_csrc[j + 3];
                        float4 v0 = ((const float4*)(rel_prev + (size_t)s0 * DIM))[lane];
                        float4 v1 = ((const float4*)(rel_prev + (size_t)s1 * DIM))[lane];
                        float4 v2 = ((const float4*)(rel_prev + (size_t)s2 * DIM))[lane];
                        float4 v3 = ((const float4*)(rel_prev + (size_t)s3 * DIM))[lane];
                        v.x += v0.x + v1.x + v2.x + v3.x;
                        v.y += v0.y + v1.y + v2.y + v3.y;
                        v.z += v0.z + v1.z + v2.z + v3.z;
                        v.w += v0.w + v1.w + v2.w + v3.w;
                    }
                    for (; j < end; j++) {
                        int s = g_csrc[j];
                        float4 vv = ((const float4*)(rel_prev + (size_t)s * DIM))[lane];
                        v.x += vv.x; v.y += vv.y; v.z += vv.z; v.w += vv.w;
                    }
                    v.x = fmaxf(v.x, 0.f); v.y = fmaxf(v.y, 0.f);
                    v.z = fmaxf(v.z, 0.f); v.w = fmaxf(v.w, 0.f);
                }
            }
            uint32_t h0, l0, h1, l1;
            split2(v.x, v.y, h0, l0);
            split2(v.z, v.w, h1, l1);
            *(uint2*)(ahi + r * SMP2 + lane * 4) = make_uint2(h0, h1);
            *(uint2*)(alo + r * SMP2 + lane * 4) = make_uint2(l0, l1);
        }
    }
    __syncwarp();   // warp-local A strip ready; no block sync needed

    // per-lane ldmatrix base offsets
    const int li = lane & 15;
    // A (x4): 16 rows (lane%16), k-halves by lane/16 — warp's own strip only
    const uint32_t a_off = (uint32_t)((wid * 16 + li) * SMP2 * 2 + (lane >> 4) * 16);
    // B (x4): matrices 0,1 = n-block nb (k-halves), 2,3 = nb+1
    const uint32_t b_off = (uint32_t)((lane & 7) * SMP2 * 2 +
                                      ((lane >> 3) & 1) * 16 +
                                      (lane >> 4) * 8 * SMP2 * 2);

    const uint32_t aHi = smb + a_off;
    const uint32_t aLo = smb + TILE_BYTES + a_off;

    const int grp = lane >> 2, q = lane & 3;
    const int row0 = m0 + wid * 16 + grp;

    #pragma unroll
    for (int phase = 0; phase < 2; phase++) {
        float acc[16][4];
        #pragma unroll
        for (int nb = 0; nb < 16; nb++)
            #pragma unroll
            for (int j = 0; j < 4; j++) acc[nb][j] = 0.f;

        const uint32_t wHi = smb + (2 + 2 * phase) * TILE_BYTES + b_off;
        const uint32_t wLo = wHi + TILE_BYTES;

        #pragma unroll
        for (int t = 0; t < 3; t++) {
            const uint32_t abase = (t == 2) ? aLo : aHi;
            const uint32_t wbase = (t == 1) ? wLo : wHi;
            #pragma unroll
            for (int ks = 0; ks < 8; ks++) {
                uint32_t a0, a1, a2, a3;
                ldsm_x4(a0, a1, a2, a3, abase + ks * 32);
                #pragma unroll
                for (int nb = 0; nb < 16; nb += 2) {
                    uint32_t b0, b1, b2, b3;
                    ldsm_x4(b0, b1, b2, b3,
                            wbase + nb * 8 * SMP2 * 2 + ks * 32);
                    mma_bf16(acc[nb],     a0, a1, a2, a3, b0, b1);
                    mma_bf16(acc[nb + 1], a0, a1, a2, a3, b2, b3);
                }
            }
        }

        float* outp = phase ? rt_out : rel_out;
        #pragma unroll
        for (int nb = 0; nb < 16; nb++) {
            int col = nb * 8 + q * 2;
            float c0 = acc[nb][0], c1 = acc[nb][1];
            float c2 = acc[nb][2], c3 = acc[nb][3];
            if (phase) {
                float bb0 = bias[col], bb1 = bias[col + 1];
                c0 += bb0; c1 += bb1; c2 += bb0; c3 += bb1;
            }
            if (row0 < N_NODES)
                *(float2*)(outp + (size_t)row0 * DIM + col) = make_float2(c0, c1);
            if (row0 + 8 < N_NODES)
                *(float2*)(outp + (size_t)(row0 + 8) * DIM + col) = make_float2(c2, c3);
        }
    }
}

// ---------------------------------------------------------------------------
// CSR build (once per launch)
// ---------------------------------------------------------------------------
__global__ void deg_zero_kernel()
{
    int i = blockIdx.x * blockDim.x + threadIdx.x;
    if (i < N_NODES) g_deg[i] = 0;
}

__global__ void deg_hist_kernel(const int* __restrict__ ei)
{
    int e = blockIdx.x * blockDim.x + threadIdx.x;
    if (e < E_EDGES) atomicAdd(&g_deg[ei[E_EDGES + e]], 1);
}

// Single-block chunked scan: thread-local sums, warp-shuffle scan, replay.
__global__ __launch_bounds__(1024)
void scan_kernel()
{
    const int T  = 1024;
    const int CH = (N_NODES + T - 1) / T;   // 49
    const int t    = threadIdx.x;
    const int lane = t & 31;
    const int wrp  = t >> 5;
    int beg = t * CH;
    int end = beg + CH; if (end > N_NODES) end = N_NODES;
    if (beg > N_NODES) beg = N_NODES;

    int sum = 0;
    for (int i = beg; i < end; i++) sum += g_deg[i];

    int v = sum;
    #pragma unroll
    for (int off = 1; off < 32; off <<= 1) {
        int u = __shfl_up_sync(0xffffffffu, v, off);
        if (lane >= off) v += u;
    }
    __shared__ int wsum[32];
    if (lane == 31) wsum[wrp] = v;
    __syncthreads();
    if (wrp == 0) {
        int w = wsum[lane];
        #pragma unroll
        for (int off = 1; off < 32; off <<= 1) {
            int u = __shfl_up_sync(0xffffffffu, w, off);
            if (lane >= off) w += u;
        }
        wsum[lane] = w;
    }
    __syncthreads();

    int base = v - sum + (wrp ? wsum[wrp - 1] : 0);
    int run = base;
    for (int i = beg; i < end; i++) {
        int d = g_deg[i];
        g_rowptr[i] = run;
        g_cursor[i] = run;
        run += d;
    }
    if (t == T - 1) g_rowptr[N_NODES] = run;
}

__global__ void fill_kernel(const int* __restrict__ ei)
{
    int e = blockIdx.x * blockDim.x + threadIdx.x;
    if (e < E_EDGES) {
        int d = ei[E_EDGES + e];
        int pos = atomicAdd(&g_cursor[d], 1);
        g_csrc[pos] = ei[e];
    }
}

// ---------------------------------------------------------------------------
// Final gather (layer 3 only): one warp per dst node, pure store into agg.
// ---------------------------------------------------------------------------
__global__ __launch_bounds__(256)
void gather_kernel(const float* __restrict__ rel,
                   float* __restrict__ agg)
{
    int w    = (blockIdx.x * blockDim.x + threadIdx.x) >> 5;
    int lane = threadIdx.x & 31;
    if (w >= N_NODES) return;
    int beg = g_rowptr[w];
    int end = g_rowptr[w + 1];

    float4 acc = make_float4(0.f, 0.f, 0.f, 0.f);
    int i = beg;
    for (; i + 4 <= end; i += 4) {
        int s0 = g_csrc[i + 0];
        int s1 = g_csrc[i + 1];
        int s2 = g_csrc[i + 2];
        int s3 = g_csrc[i + 3];
        float4 v0 = ((const float4*)(rel + (size_t)s0 * DIM))[lane];
        float4 v1 = ((const float4*)(rel + (size_t)s1 * DIM))[lane];
        float4 v2 = ((const float4*)(rel + (size_t)s2 * DIM))[lane];
        float4 v3 = ((const float4*)(rel + (size_t)s3 * DIM))[lane];
        acc.x += v0.x + v1.x + v2.x + v3.x;
        acc.y += v0.y + v1.y + v2.y + v3.y;
        acc.z += v0.z + v1.z + v2.z + v3.z;
        acc.w += v0.w + v1.w + v2.w + v3.w;
    }
    for (; i < end; i++) {
        int s = g_csrc[i];
        float4 v = ((const float4*)(rel + (size_t)s * DIM))[lane];
        acc.x += v.x; acc.y += v.y; acc.z += v.z; acc.w += v.w;
    }
    ((float4*)(agg + (size_t)w * DIM))[lane] = acc;
}

// ---------------------------------------------------------------------------
__global__ void zero_kernel()
{
    int i = blockIdx.x * blockDim.x + threadIdx.x;
    if (i < G_GRAPHS * DIM) g_pool[i] = 0.f;
    if (i < G_GRAPHS) g_cnt[i] = 0.f;
}

// Mean pool over relu(rt+agg), run-length on sorted batch.
__global__ __launch_bounds__(128)
void pool2_kernel(const float* __restrict__ rt,
                  const float* __restrict__ agg,
                  const int* __restrict__ batch)
{
    int f  = threadIdx.x;
    int n0 = blockIdx.x * 64;
    int n1 = n0 + 64;
    if (n1 > N_NODES) n1 = N_NODES;

    int cur = batch[n0];
    float acc = 0.f;
    for (int n = n0; n < n1; n++) {
        int b = batch[n];
        if (b != cur) {
            atomicAdd(&g_pool[cur * DIM + f], acc);
            acc = 0.f;
            cur = b;
        }
        float hv = rt[(size_t)n * DIM + f] + agg[(size_t)n * DIM + f];
        acc += fmaxf(hv, 0.f);
    }
    atomicAdd(&g_pool[cur * DIM + f], acc);

    if (f == 0) {
        int c2 = batch[n0];
        float c = 0.f;
        for (int n = n0; n < n1; n++) {
            int b = batch[n];
            if (b != c2) { atomicAdd(&g_cnt[c2], c); c = 0.f; c2 = b; }
            c += 1.f;
        }
        atomicAdd(&g_cnt[c2], c);
    }
}

__global__ __launch_bounds__(128)
void final_kernel(const float* __restrict__ lw,
                  const float* __restrict__ lb,
                  float* __restrict__ out)
{
    __shared__ float red[4];
    int g = blockIdx.x;
    int t = threadIdx.x;
    float c = fmaxf(g_cnt[g], 1.0f);
    float v = g_pool[g * DIM + t] / c;
    for (int cc = 0; cc < C_CLASSES; cc++) {
        float p = v * lw[cc * DIM + t];
        #pragma unroll
        for (int off = 16; off; off >>= 1)
            p += __shfl_down_sync(0xffffffffu, p, off);
        if ((t & 31) == 0) red[t >> 5] = p;
        __syncthreads();
        if (t == 0)
            out[g * C_CLASSES + cc] = red[0] + red[1] + red[2] + red[3] + lb[cc];
        __syncthreads();
    }
}

// ---------------------------------------------------------------------------
extern "C" void kernel_launch(void* const* d_in, const int* in_sizes, int n_in,
                              void* d_out, int out_size)
{
    const float* x     = (const float*)d_in[0];
    const int*   ei    = (const int*)d_in[1];
    const int*   batch = (const int*)d_in[2];
    const float* Wrel[4]  = {(const float*)d_in[3], (const float*)d_in[6],
                             (const float*)d_in[9], (const float*)d_in[12]};
    const float* brel[4]  = {(const float*)d_in[4], (const float*)d_in[7],
                             (const float*)d_in[10], (const float*)d_in[13]};
    const float* Wroot[4] = {(const float*)d_in[5], (const float*)d_in[8],
                             (const float*)d_in[11], (const float*)d_in[14]};
    const float* lin_w = (const float*)d_in[15];
    const float* lin_b = (const float*)d_in[16];
    float* out = (float*)d_out;

    float *relA, *relB, *rtA, *rtB;
    cudaGetSymbolAddress((void**)&relA, g_relA);
    cudaGetSymbolAddress((void**)&relB, g_relB);
    cudaGetSymbolAddress((void**)&rtA,  g_rtA);
    cudaGetSymbolAddress((void**)&rtB,  g_rtB);

    const int SM_TOTAL = 6 * TILE_BYTES;   // 208896 B
    cudaFuncSetAttribute(gemm_fused_kernel,
                         cudaFuncAttributeMaxDynamicSharedMemorySize, SM_TOTAL);

    // Pre-convert weights (hi/lo padded images), once per launch
    WPtrs wp;
    for (int i = 0; i < 4; i++) { wp.p[2 * i] = Wrel[i]; wp.p[2 * i + 1] = Wroot[i]; }
    w_convert_kernel<<<8, 256>>>(wp);

    // Build CSR once
    deg_zero_kernel<<<(N_NODES + 255) / 256, 256>>>();
    deg_hist_kernel<<<(E_EDGES + 255) / 256, 256>>>(ei);
    scan_kernel<<<1, 1024>>>();
    fill_kernel<<<(E_EDGES + 255) / 256, 256>>>(ei);
    zero_kernel<<<(G_GRAPHS * DIM + 255) / 256, 256>>>();

    const int GGRID = (N_NODES + TILE_M - 1) / TILE_M;    // 391
    const int GTH   = (N_NODES * 32 + 255) / 256;

    // Layers (gather fused into each layer's A staging):
    // L0: A=x            -> relA, rtA
    // L1: A=f(rtA,relA)  -> relB, rtB
    // L2: A=f(rtB,relB)  -> relA, rtA
    // L3: A=f(rtA,relA)  -> relB, rtB
    gemm_fused_kernel<<<GGRID, 256, SM_TOTAL>>>(x, nullptr, nullptr, brel[0],
                                                relA, rtA, 0);
    gemm_fused_kernel<<<GGRID, 256, SM_TOTAL>>>(nullptr, relA, rtA, brel[1],
                                                relB, rtB, 1);
    gemm_fused_kernel<<<GGRID, 256, SM_TOTAL>>>(nullptr, relB, rtB, brel[2],
                                                relA, rtA, 2);
    gemm_fused_kernel<<<GGRID, 256, SM_TOTAL>>>(nullptr, relA, rtA, brel[3],
                                                relB, rtB, 3);

    // Final: agg = gather(relB) (reuse relA as agg), pool relu(rtB+agg), head
    gather_kernel<<<GTH, 256>>>(relB, relA);
    pool2_kernel<<<(N_NODES + 63) / 64, 128>>>(rtB, relA, batch);
    final_kernel<<<G_GRAPHS, 128>>>(lin_w, lin_b, out);
}

// round 17
// speedup vs baseline: 1.5122x; 1.5122x over previous
#include <cuda_runtime.h>
#include <cuda_bf16.h>
#include <cstdint>

#define N_NODES 50000
#define E_EDGES 800000
#define DIM     128
#define G_GRAPHS 128
#define C_CLASSES 10
#define TILE_M  128
#define SMP2    136                     // padded bf16 row stride (272 B)
#define TILE_ELEMS (TILE_M * SMP2)      // 17408 bf16
#define TILE_BYTES (TILE_ELEMS * 2)     // 34816 B

// ---------------------------------------------------------------------------
// Device scratch (no allocation allowed)
// ---------------------------------------------------------------------------
__device__ float g_bufA[N_NODES * DIM];
__device__ float g_bufB[N_NODES * DIM];
__device__ float g_rel [N_NODES * DIM];
__device__ float g_pool[G_GRAPHS * DIM];
__device__ float g_cnt [G_GRAPHS];
// CSR scratch
__device__ int g_deg   [N_NODES];
__device__ int g_rowptr[N_NODES + 1];
__device__ int g_cursor[N_NODES];
__device__ int g_csrc  [E_EDGES];
// Pre-converted W images, padded rows (SMP2), order per layer:
// [2*layer][0]=rel hi, [2*layer][1]=rel lo, [2*layer+1][0]=root hi, [1]=root lo
__device__ __nv_bfloat16 g_wimg[8][2][TILE_ELEMS];

// ---------------------------------------------------------------------------
// helpers
// ---------------------------------------------------------------------------
__device__ __forceinline__ uint32_t smem_u32(const void* p) {
    uint32_t a;
    asm("{ .reg .u64 t; cvta.to.shared.u64 t, %1; cvt.u32.u64 %0, t; }"
        : "=r"(a) : "l"(p));
    return a;
}

// split fp32 pair -> bf16 hi pair + bf16 lo pair (packed: first arg in low half)
__device__ __forceinline__ void split2(float a, float b, uint32_t& hi, uint32_t& lo) {
    asm("cvt.rn.bf16x2.f32 %0, %1, %2;" : "=r"(hi) : "f"(b), "f"(a));
    float ra = a - __uint_as_float(hi << 16);
    float rb = b - __uint_as_float(hi & 0xffff0000u);
    asm("cvt.rn.bf16x2.f32 %0, %1, %2;" : "=r"(lo) : "f"(rb), "f"(ra));
}

__device__ __forceinline__ void ldsm_x4(uint32_t& a0, uint32_t& a1,
                                        uint32_t& a2, uint32_t& a3, uint32_t addr) {
    asm volatile("ldmatrix.sync.aligned.m8n8.x4.shared.b16 {%0,%1,%2,%3}, [%4];"
                 : "=r"(a0), "=r"(a1), "=r"(a2), "=r"(a3) : "r"(addr));
}
__device__ __forceinline__ void mma_bf16(float* c, uint32_t a0, uint32_t a1,
                                         uint32_t a2, uint32_t a3,
                                         uint32_t b0, uint32_t b1) {
    asm volatile("mma.sync.aligned.m16n8k16.row.col.f32.bf16.bf16.f32 "
                 "{%0,%1,%2,%3}, {%4,%5,%6,%7}, {%8,%9}, {%0,%1,%2,%3};"
                 : "+f"(c[0]), "+f"(c[1]), "+f"(c[2]), "+f"(c[3])
                 : "r"(a0), "r"(a1), "r"(a2), "r"(a3), "r"(b0), "r"(b1));
}

// ---------------------------------------------------------------------------
// W pre-convert: 8 blocks, one per (layer, mat). fp32 -> bf16 hi/lo, padded rows.
// ---------------------------------------------------------------------------
struct WPtrs { const float* p[8]; };

__global__ __launch_bounds__(256)
void w_convert_kernel(WPtrs wp)
{
    int b = blockIdx.x;
    const float* src = wp.p[b];
    __nv_bfloat16* hi_img = &g_wimg[b][0][0];
    __nv_bfloat16* lo_img = &g_wimg[b][1][0];
    int tid = threadIdx.x;
    #pragma unroll
    for (int it = 0; it < 16; it++) {
        int id = tid + it * 256;        // 0..4095 quads
        int r = id >> 5;
        int c = (id & 31) * 4;
        float4 v = *(const float4*)(src + r * DIM + c);
        uint32_t h0, l0, h1, l1;
        split2(v.x, v.y, h0, l0);
        split2(v.z, v.w, h1, l1);
        *(uint2*)(hi_img + r * SMP2 + c) = make_uint2(h0, h1);
        *(uint2*)(lo_img + r * SMP2 + c) = make_uint2(l0, l1);
    }
}

// ---------------------------------------------------------------------------
// HMMA GEMM pair: one block per 128-row slab of A.
//   rel[n,o]  = act(A)[n,:] . Wrel[o,:]
//   next[n,o] = act(A)[n,:] . Wroot[o,:] + bias[o]
// Split-bf16, 3 terms: Ahi*Whi + Ahi*Wlo + Alo*Whi (fp32 accum).
// smem tiles (bf16, padded SMP2): [0]=Ahi [1]=Alo [2]=Wrel_hi [3]=Wrel_lo
// [4]=Wroot_hi [5]=Wroot_lo   — tiles 2..5 are one contiguous copy from g_wimg.
// B loads use ldmatrix.x4 pairing two adjacent n-blocks.
// ---------------------------------------------------------------------------
__global__ __launch_bounds__(256, 1)
void gemm_mma_kernel(const float* __restrict__ A,
                     const float* __restrict__ bias,
                     float* __restrict__ rel_out,
                     float* __restrict__ next_out,
                     int layer, int apply_relu)
{
    extern __shared__ __align__(16) char sm[];
    __nv_bfloat16* tiles = (__nv_bfloat16*)sm;
    const uint32_t smb = smem_u32(sm);
    const int tid  = threadIdx.x;
    const int wid  = tid >> 5;
    const int lane = tid & 31;
    const int m0   = blockIdx.x * TILE_M;

    // --- copy 4 W tiles (contiguous in g_wimg) ---
    {
        const uint4* src = (const uint4*)&g_wimg[2 * layer][0][0];
        uint4* dst = (uint4*)(tiles + 2 * TILE_ELEMS);
        #pragma unroll
        for (int it = 0; it < 34; it++)
            dst[tid + it * 256] = src[tid + it * 256];   // 8704 uint4 total
    }

    // --- A convert: fp32 (+ReLU) -> bf16 hi/lo, padded rows ---
    {
        __nv_bfloat16* ahi = tiles;
        __nv_bfloat16* alo = tiles + TILE_ELEMS;
        #pragma unroll
        for (int it = 0; it < 16; it++) {
            int id = tid + it * 256;        // 0..4095 quads
            int r = id >> 5;
            int c = (id & 31) * 4;
            int row = m0 + r;
            float4 v = make_float4(0.f, 0.f, 0.f, 0.f);
            if (row < N_NODES) v = *(const float4*)(A + (size_t)row * DIM + c);
            if (apply_relu) {
                v.x = fmaxf(v.x, 0.f); v.y = fmaxf(v.y, 0.f);
                v.z = fmaxf(v.z, 0.f); v.w = fmaxf(v.w, 0.f);
            }
            uint32_t h0, l0, h1, l1;
            split2(v.x, v.y, h0, l0);
            split2(v.z, v.w, h1, l1);
            *(uint2*)(ahi + r * SMP2 + c) = make_uint2(h0, h1);
            *(uint2*)(alo + r * SMP2 + c) = make_uint2(l0, l1);
        }
    }
    __syncthreads();

    // per-lane ldmatrix base offsets
    const int li = lane & 15;
    // A (x4, 16 lanes used): 16 rows (lane%16), k-halves by lane/16
    const uint32_t a_off = (uint32_t)((wid * 16 + li) * SMP2 * 2 + (lane >> 4) * 16);
    // B (x4, all 32 lanes): matrices 0,1 = n-block nb (k-halves), 2,3 = nb+1
    const uint32_t b_off = (uint32_t)((lane & 7) * SMP2 * 2 +
                                      ((lane >> 3) & 1) * 16 +
                                      (lane >> 4) * 8 * SMP2 * 2);

    const uint32_t aHi = smb + a_off;
    const uint32_t aLo = smb + TILE_BYTES + a_off;

    const int grp = lane >> 2, q = lane & 3;
    const int row0 = m0 + wid * 16 + grp;

    #pragma unroll
    for (int phase = 0; phase < 2; phase++) {
        float acc[16][4];
        #pragma unroll
        for (int nb = 0; nb < 16; nb++)
            #pragma unroll
            for (int j = 0; j < 4; j++) acc[nb][j] = 0.f;

        const uint32_t wHi = smb + (2 + 2 * phase) * TILE_BYTES + b_off;
        const uint32_t wLo = wHi + TILE_BYTES;

        #pragma unroll
        for (int t = 0; t < 3; t++) {
            const uint32_t abase = (t == 2) ? aLo : aHi;
            const uint32_t wbase = (t == 1) ? wLo : wHi;
            #pragma unroll
            for (int ks = 0; ks < 8; ks++) {
                uint32_t a0, a1, a2, a3;
                ldsm_x4(a0, a1, a2, a3, abase + ks * 32);
                #pragma unroll
                for (int nb = 0; nb < 16; nb += 2) {
                    uint32_t b0, b1, b2, b3;
                    ldsm_x4(b0, b1, b2, b3,
                            wbase + nb * 8 * SMP2 * 2 + ks * 32);
                    mma_bf16(acc[nb],     a0, a1, a2, a3, b0, b1);
                    mma_bf16(acc[nb + 1], a0, a1, a2, a3, b2, b3);
                }
            }
        }

        float* outp = phase ? next_out : rel_out;
        #pragma unroll
        for (int nb = 0; nb < 16; nb++) {
            int col = nb * 8 + q * 2;
            float c0 = acc[nb][0], c1 = acc[nb][1];
            float c2 = acc[nb][2], c3 = acc[nb][3];
            if (phase) {
                float bb0 = bias[col], bb1 = bias[col + 1];
                c0 += bb0; c1 += bb1; c2 += bb0; c3 += bb1;
            }
            if (row0 < N_NODES)
                *(float2*)(outp + (size_t)row0 * DIM + col) = make_float2(c0, c1);
            if (row0 + 8 < N_NODES)
                *(float2*)(outp + (size_t)(row0 + 8) * DIM + col) = make_float2(c2, c3);
        }
    }
}

// ---------------------------------------------------------------------------
// CSR build (once per launch)
// ---------------------------------------------------------------------------
__global__ void deg_zero_kernel()
{
    int i = blockIdx.x * blockDim.x + threadIdx.x;
    if (i < N_NODES) g_deg[i] = 0;
}

__global__ void deg_hist_kernel(const int* __restrict__ ei)
{
    int e = blockIdx.x * blockDim.x + threadIdx.x;
    if (e < E_EDGES) atomicAdd(&g_deg[ei[E_EDGES + e]], 1);
}

// Single-block chunked scan: thread-local sums, warp-shuffle scan, replay.
__global__ __launch_bounds__(1024)
void scan_kernel()
{
    const int T  = 1024;
    const int CH = (N_NODES + T - 1) / T;   // 49
    const int t    = threadIdx.x;
    const int lane = t & 31;
    const int wrp  = t >> 5;
    int beg = t * CH;
    int end = beg + CH; if (end > N_NODES) end = N_NODES;
    if (beg > N_NODES) beg = N_NODES;

    int sum = 0;
    for (int i = beg; i < end; i++) sum += g_deg[i];

    int v = sum;
    #pragma unroll
    for (int off = 1; off < 32; off <<= 1) {
        int u = __shfl_up_sync(0xffffffffu, v, off);
        if (lane >= off) v += u;
    }
    __shared__ int wsum[32];
    if (lane == 31) wsum[wrp] = v;
    __syncthreads();
    if (wrp == 0) {
        int w = wsum[lane];
        #pragma unroll
        for (int off = 1; off < 32; off <<= 1) {
            int u = __shfl_up_sync(0xffffffffu, w, off);
            if (lane >= off) w += u;
        }
        wsum[lane] = w;
    }
    __syncthreads();

    int base = v - sum + (wrp ? wsum[wrp - 1] : 0);
    int run = base;
    for (int i = beg; i < end; i++) {
        int d = g_deg[i];
        g_rowptr[i] = run;
        g_cursor[i] = run;
        run += d;
    }
    if (t == T - 1) g_rowptr[N_NODES] = run;
}

__global__ void fill_kernel(const int* __restrict__ ei)
{
    int e = blockIdx.x * blockDim.x + threadIdx.x;
    if (e < E_EDGES) {
        int d = ei[E_EDGES + e];
        int pos = atomicAdd(&g_cursor[d], 1);
        g_csrc[pos] = ei[e];
    }
}

// ---------------------------------------------------------------------------
// Gather: one warp per dst node (atomic-free). next[d] += sum rel[src].
// 4-way batching (8-way regressed: L1tex queue contention).
// ---------------------------------------------------------------------------
__global__ __launch_bounds__(256)
void gather_kernel(const float* __restrict__ rel,
                   float* __restrict__ next)
{
    int w    = (blockIdx.x * blockDim.x + threadIdx.x) >> 5;
    int lane = threadIdx.x & 31;
    if (w >= N_NODES) return;
    int beg = g_rowptr[w];
    int end = g_rowptr[w + 1];

    float4 acc = make_float4(0.f, 0.f, 0.f, 0.f);
    int i = beg;
    for (; i + 4 <= end; i += 4) {
        int s0 = g_csrc[i + 0];
        int s1 = g_csrc[i + 1];
        int s2 = g_csrc[i + 2];
        int s3 = g_csrc[i + 3];
        float4 v0 = ((const float4*)(rel + (size_t)s0 * DIM))[lane];
        float4 v1 = ((const float4*)(rel + (size_t)s1 * DIM))[lane];
        float4 v2 = ((const float4*)(rel + (size_t)s2 * DIM))[lane];
        float4 v3 = ((const float4*)(rel + (size_t)s3 * DIM))[lane];
        acc.x += v0.x + v1.x + v2.x + v3.x;
        acc.y += v0.y + v1.y + v2.y + v3.y;
        acc.z += v0.z + v1.z + v2.z + v3.z;
        acc.w += v0.w + v1.w + v2.w + v3.w;
    }
    for (; i < end; i++) {
        int s = g_csrc[i];
        float4 v = ((const float4*)(rel + (size_t)s * DIM))[lane];
        acc.x += v.x; acc.y += v.y; acc.z += v.z; acc.w += v.w;
    }

    float4* p = (float4*)(next + (size_t)w * DIM) + lane;
    float4 o = *p;
    o.x += acc.x; o.y += acc.y; o.z += acc.z; o.w += acc.w;
    *p = o;
}

// ---------------------------------------------------------------------------
__global__ void zero_kernel(float* __restrict__ pool, float* __restrict__ cnt)
{
    int i = blockIdx.x * blockDim.x + threadIdx.x;
    if (i < G_GRAPHS * DIM) pool[i] = 0.f;
    if (i < G_GRAPHS) cnt[i] = 0.f;
}

__global__ __launch_bounds__(128)
void pool_kernel(const float* __restrict__ h,
                 const int* __restrict__ batch,
                 float* __restrict__ pool,
                 float* __restrict__ cnt)
{
    int f  = threadIdx.x;
    int n0 = blockIdx.x * 64;
    int n1 = n0 + 64;
    if (n1 > N_NODES) n1 = N_NODES;

    int cur = batch[n0];
    float acc = 0.f;
    for (int n = n0; n < n1; n++) {
        int b = batch[n];
        if (b != cur) {
            atomicAdd(&pool[cur * DIM + f], acc);
            acc = 0.f;
            cur = b;
        }
        acc += fmaxf(h[(size_t)n * DIM + f], 0.f);
    }
    atomicAdd(&pool[cur * DIM + f], acc);

    if (f == 0) {
        int c2 = batch[n0];
        float c = 0.f;
        for (int n = n0; n < n1; n++) {
            int b = batch[n];
            if (b != c2) { atomicAdd(&cnt[c2], c); c = 0.f; c2 = b; }
            c += 1.f;
        }
        atomicAdd(&cnt[c2], c);
    }
}

__global__ __launch_bounds__(128)
void final_kernel(const float* __restrict__ pool,
                  const float* __restrict__ cnt,
                  const float* __restrict__ lw,
                  const float* __restrict__ lb,
                  float* __restrict__ out)
{
    __shared__ float red[4];
    int g = blockIdx.x;
    int t = threadIdx.x;
    float c = fmaxf(cnt[g], 1.0f);
    float v = pool[g * DIM + t] / c;
    for (int cc = 0; cc < C_CLASSES; cc++) {
        float p = v * lw[cc * DIM + t];
        #pragma unroll
        for (int off = 16; off; off >>= 1)
            p += __shfl_down_sync(0xffffffffu, p, off);
        if ((t & 31) == 0) red[t >> 5] = p;
        __syncthreads();
        if (t == 0)
            out[g * C_CLASSES + cc] = red[0] + red[1] + red[2] + red[3] + lb[cc];
        __syncthreads();
    }
}

// ---------------------------------------------------------------------------
extern "C" void kernel_launch(void* const* d_in, const int* in_sizes, int n_in,
                              void* d_out, int out_size)
{
    const float* x     = (const float*)d_in[0];
    const int*   ei    = (const int*)d_in[1];
    const int*   batch = (const int*)d_in[2];
    const float* Wrel[4]  = {(const float*)d_in[3], (const float*)d_in[6],
                             (const float*)d_in[9], (const float*)d_in[12]};
    const float* brel[4]  = {(const float*)d_in[4], (const float*)d_in[7],
                             (const float*)d_in[10], (const float*)d_in[13]};
    const float* Wroot[4] = {(const float*)d_in[5], (const float*)d_in[8],
                             (const float*)d_in[11], (const float*)d_in[14]};
    const float* lin_w = (const float*)d_in[15];
    const float* lin_b = (const float*)d_in[16];
    float* out = (float*)d_out;

    float *bufA, *bufB, *rel, *pool, *cnt;
    cudaGetSymbolAddress((void**)&bufA, g_bufA);
    cudaGetSymbolAddress((void**)&bufB, g_bufB);
    cudaGetSymbolAddress((void**)&rel,  g_rel);
    cudaGetSymbolAddress((void**)&pool, g_pool);
    cudaGetSymbolAddress((void**)&cnt,  g_cnt);

    // lazily-created side stream + events (first call is the non-captured
    // correctness run; capture call reuses the handles — fork/join pattern,
    // validated under graph capture in round 12)
    static cudaStream_t s2 = nullptr;
    static cudaEvent_t evS = nullptr, evC = nullptr;
    if (!s2) {
        cudaStreamCreateWithFlags(&s2, cudaStreamNonBlocking);
        cudaEventCreateWithFlags(&evS, cudaEventDisableTiming);
        cudaEventCreateWithFlags(&evC, cudaEventDisableTiming);
    }

    const int SM_TOTAL = 6 * TILE_BYTES;   // 208896 B
    cudaFuncSetAttribute(gemm_mma_kernel,
                         cudaFuncAttributeMaxDynamicSharedMemorySize, SM_TOTAL);

    const int GGRID = (N_NODES + TILE_M - 1) / TILE_M;    // 391
    const int GTH   = (N_NODES * 32 + 255) / 256;

    // ---- fork: CSR build + pool-zero on side stream (independent of gemm0) ----
    cudaEventRecord(evS, 0);
    cudaStreamWaitEvent(s2, evS, 0);
    deg_zero_kernel<<<(N_NODES + 255) / 256, 256, 0, s2>>>();
    deg_hist_kernel<<<(E_EDGES + 255) / 256, 256, 0, s2>>>(ei);
    scan_kernel<<<1, 1024, 0, s2>>>();
    fill_kernel<<<(E_EDGES + 255) / 256, 256, 0, s2>>>(ei);
    zero_kernel<<<(G_GRAPHS * DIM + 255) / 256, 256, 0, s2>>>(pool, cnt);
    cudaEventRecord(evC, s2);

    // ---- origin: W pre-convert + layer-0 GEMM (no CSR dependency) ----
    WPtrs wp;
    for (int i = 0; i < 4; i++) { wp.p[2 * i] = Wrel[i]; wp.p[2 * i + 1] = Wroot[i]; }
    w_convert_kernel<<<8, 256>>>(wp);
    gemm_mma_kernel<<<GGRID, 256, SM_TOTAL>>>(x, brel[0], rel, bufA, 0, 0);

    // ---- join: gather needs CSR ----
    cudaStreamWaitEvent(0, evC, 0);

    const float* h = bufA;
    gather_kernel<<<GTH, 256>>>(rel, bufA);
    for (int i = 1; i < 4; i++) {
        float* nxt = (i & 1) ? bufB : bufA;
        gemm_mma_kernel<<<GGRID, 256, SM_TOTAL>>>(h, brel[i], rel, nxt, i, 1);
        gather_kernel<<<GTH, 256>>>(rel, nxt);
        h = nxt;
    }

    pool_kernel<<<(N_NODES + 63) / 64, 128>>>(h, batch, pool, cnt);
    final_kernel<<<G_GRAPHS, 128>>>(pool, cnt, lin_w, lin_b, out);
}